// round 5
// baseline (speedup 1.0000x reference)
#include <cuda_runtime.h>

typedef unsigned long long ull;

#define TILE    32
#define HALO    5
#define KW      11
#define REGN    42          // TILE + 2*HALO
#define PP      43          // sxy pitch in (u,v) pairs (ull)
#define HP      33          // h-buffer pitch in float4
#define IMH     2048
#define IMW     2048
#define NCH     3
#define NTHREADS 256
#define NTILES  64

#define C1 1.0e-4f
#define C2 9.0e-4f

// per-channel smem layout (floats)
#define OFS_SXY  0                              // REGN*PP ull = 3612 floats
#define OFS_H    (REGN*PP*2)                    // 3612
#define SMEM_FLOATS (OFS_H + REGN*HP*4)         // +5544 = 9156 (36624 B)

__device__ float g_partial[NTILES * NTILES];
__device__ unsigned int g_flag;   // zero-init; last block resets it

__device__ __forceinline__ ull pack2(float lo, float hi) {
    ull r; asm("mov.b64 %0,{%1,%2};" : "=l"(r) : "f"(lo), "f"(hi)); return r;
}
__device__ __forceinline__ float2 unpack2(ull v) {
    float2 r; asm("mov.b64 {%0,%1},%2;" : "=f"(r.x), "=f"(r.y) : "l"(v)); return r;
}
__device__ __forceinline__ ull fma2(ull a, ull b, ull c) {
    ull d; asm("fma.rn.f32x2 %0,%1,%2,%3;" : "=l"(d) : "l"(a), "l"(b), "l"(c)); return d;
}
__device__ __forceinline__ ull mul2(ull a, ull b) {
    ull d; asm("mul.rn.f32x2 %0,%1,%2;" : "=l"(d) : "l"(a), "l"(b)); return d;
}

// load one channel's (u,v) halo tile with nwarps warps starting at wstart
__device__ __forceinline__ void load_channel(
    const float* __restrict__ img1, const float* __restrict__ img2,
    float* __restrict__ sxyF, int c, int row0, int col0,
    int wrel, int nwarps, int lane)
{
    for (int r = wrel; r < REGN; r += nwarps) {
        int gr = row0 + r;
        bool rok = (gr >= 0 && gr < IMH);
        {
            int p = lane;
            int gc = col0 + p;
            float v1 = 0.f, v2 = 0.f;
            if (rok && gc >= 0 && gc < IMW) {
                int off = (gr * IMW + gc) * NCH + c;
                v1 = img1[off]; v2 = img2[off];
            }
            ((float2*)sxyF)[r * PP + p] = make_float2(v1 + v2, v1 - v2);
        }
        if (lane < REGN - 32) {
            int p = 32 + lane;
            int gc = col0 + p;
            float v1 = 0.f, v2 = 0.f;
            if (rok && gc >= 0 && gc < IMW) {
                int off = (gr * IMW + gc) * NCH + c;
                v1 = img1[off]; v2 = img2[off];
            }
            ((float2*)sxyF)[r * PP + p] = make_float2(v1 + v2, v1 - v2);
        }
    }
}

__global__ __launch_bounds__(NTHREADS, 4) void ssim_tile_kernel(
    const float* __restrict__ img1,
    const float* __restrict__ img2,
    const float* __restrict__ window,
    float* __restrict__ out)
{
    extern __shared__ float smem[];
    float* sxyF = smem + OFS_SXY;                // (u,v) pairs, one channel
    float* hF   = smem + OFS_H;                  // (U,V,Su,Sv) float4 per column

    const int tid  = threadIdx.x;
    const int wid  = tid >> 5;
    const int lane = tid & 31;

    // ---- separable taps: w2d = g g^T exactly, so g_k = w2d[5][k] / sqrt(w2d[5][5])
    ull wwr[KW];                                  // (w,w) broadcast pairs in regs
    {
        float g5 = sqrtf(window[5 * KW + 5]);
        #pragma unroll
        for (int k = 0; k < KW; k++) {
            float w = window[5 * KW + k] / g5;
            wwr[k] = pack2(w, w);
        }
    }

    const int row0 = (int)blockIdx.y * TILE - HALO;
    const int col0 = (int)blockIdx.x * TILE - HALO;

    // ---- prologue: channel 0 load with all 8 warps ----
    load_channel(img1, img2, sxyF, 0, row0, col0, wid, 8, lane);
    __syncthreads();

    float lsum = 0.f;

    #pragma unroll
    for (int c = 0; c < NCH; c++) {
        // ---------- horizontal pass: 8-wide register-blocked, single wave -----
        if (tid < REGN * 4) {                     // 168 items
            int r  = tid % REGN;
            int j0 = (tid / REGN) << 3;
            const ull* puv = (const ull*)sxyF + r * PP + j0;

            ull auv[8], ass[8];
            #pragma unroll
            for (int o = 0; o < 8; o++) { auv[o] = 0; ass[o] = 0; }

            #pragma unroll
            for (int t = 0; t < 18; t++) {        // 8 + KW - 1
                ull vuv = puv[t];
                ull vss = mul2(vuv, vuv);
                #pragma unroll
                for (int o = 0; o < 8; o++) {
                    int k = t - o;
                    if (k >= 0 && k < KW) {       // compile-time resolved
                        auv[o] = fma2(wwr[k], vuv, auv[o]);
                        ass[o] = fma2(wwr[k], vss, ass[o]);
                    }
                }
            }
            float4* dst = (float4*)hF + r * HP + j0;
            #pragma unroll
            for (int o = 0; o < 8; o++) {
                float2 a = unpack2(auv[o]);
                float2 b = unpack2(ass[o]);
                dst[o] = make_float4(a.x, a.y, b.x, b.y);
            }
        }
        __syncthreads();   // sxy reads done; h writes visible

        // ---------- vertical (warps 0-3) || next-channel load (warps 4-7) -----
        if (wid < 4) {
            int tx  = lane;
            int ty0 = wid << 3;                   // 8-row stack
            ull aU[8], aS[8];
            #pragma unroll
            for (int o = 0; o < 8; o++) { aU[o] = 0; aS[o] = 0; }

            #pragma unroll
            for (int t = 0; t < 18; t++) {
                int r = ty0 + t;
                float4 h = ((const float4*)hF)[r * HP + tx];
                ull huv = pack2(h.x, h.y);
                ull hss = pack2(h.z, h.w);
                #pragma unroll
                for (int o = 0; o < 8; o++) {
                    int k = t - o;
                    if (k >= 0 && k < KW) {
                        aU[o] = fma2(wwr[k], huv, aU[o]);
                        aS[o] = fma2(wwr[k], hss, aS[o]);
                    }
                }
            }
            #pragma unroll
            for (int o = 0; o < 8; o++) {
                float2 uv = unpack2(aU[o]);      // U = mu1+mu2, V = mu1-mu2
                float2 ss = unpack2(aS[o]);      // Su = E[u^2], Sv = E[v^2]
                float U2 = uv.x * uv.x;
                float V2 = uv.y * uv.y;
                float A  = ss.x - U2;            // = s1+s2+2*s12 (x2 scale)
                float B  = ss.y - V2;            // = s1+s2-2*s12 (x2 scale)
                float num = fmaf(0.5f, U2 - V2, C1) * fmaf(0.5f, A - B, C2);
                float den = fmaf(0.5f, U2 + V2, C1) * fmaf(0.5f, A + B, C2);
                lsum += __fdividef(num, den);
            }
        } else if (c + 1 < NCH) {
            // sxy is dead after the horizontal pass: prefetch next channel
            load_channel(img1, img2, sxyF, c + 1, row0, col0, wid - 4, 4, lane);
        }
        __syncthreads();   // sxy(c+1) visible; h reads done before next horiz
    }

    // ---------- block reduction ----------
    #pragma unroll
    for (int s = 16; s > 0; s >>= 1)
        lsum += __shfl_xor_sync(0xffffffffu, lsum, s);
    __shared__ float red[8];
    if (lane == 0) red[wid] = lsum;
    __syncthreads();
    if (tid == 0) {
        float bs = 0.f;
        #pragma unroll
        for (int i = 0; i < 8; i++) bs += red[i];
        g_partial[blockIdx.y * gridDim.x + blockIdx.x] = bs;
    }

    // ---------- last-block finalize (no second launch) ----------
    __shared__ bool amLast;
    __threadfence();
    if (tid == 0) {
        unsigned int n = atomicAdd(&g_flag, 1u);
        amLast = (n == (unsigned)(NTILES * NTILES - 1));
    }
    __syncthreads();
    if (amLast) {
        double s = 0.0;
        for (int i = tid; i < NTILES * NTILES; i += NTHREADS)
            s += (double)g_partial[i];
        #pragma unroll
        for (int sft = 16; sft > 0; sft >>= 1)
            s += __shfl_xor_sync(0xffffffffu, s, sft);
        __shared__ double rd[8];
        if (lane == 0) rd[wid] = s;
        __syncthreads();
        if (tid == 0) {
            double t = 0.0;
            #pragma unroll
            for (int i = 0; i < 8; i++) t += rd[i];
            out[0] = (float)(1.0 - t / ((double)IMH * IMW * NCH));
            g_flag = 0;                 // reset for next graph replay
        }
    }
}

extern "C" void kernel_launch(void* const* d_in, const int* in_sizes, int n_in,
                              void* d_out, int out_size)
{
    const float* img1 = (const float*)d_in[0];
    const float* img2 = (const float*)d_in[1];
    const float* win  = (const float*)d_in[2];
    float* out = (float*)d_out;
    (void)in_sizes; (void)n_in; (void)out_size;

    const size_t SMEM = (size_t)SMEM_FLOATS * sizeof(float);   // 36624 B
    cudaFuncSetAttribute(ssim_tile_kernel,
                         cudaFuncAttributeMaxDynamicSharedMemorySize, (int)SMEM);

    dim3 grid(NTILES, NTILES);
    ssim_tile_kernel<<<grid, NTHREADS, SMEM>>>(img1, img2, win, out);
}

// round 6
// speedup vs baseline: 1.5112x; 1.5112x over previous
#include <cuda_runtime.h>

typedef unsigned long long ull;

#define TX      64
#define TY      32
#define HALO    5
#define KW      11
#define RX      74          // TX + 2*HALO
#define RY      42          // TY + 2*HALO
#define PP      75          // sxy pitch in (u,v) pairs (ull)
#define HP      65          // h-buffer pitch in float4
#define IMH     2048
#define IMW     2048
#define NCH     3
#define NTHREADS 256
#define GX      32          // 2048 / TX
#define GY      64          // 2048 / TY
#define NBLK    (GX*GY)

#define C1 1.0e-4f
#define C2 9.0e-4f

// per-channel smem layout (floats)
#define OFS_SXY  0                              // RY*PP ull = 6300 floats
#define OFS_H    (RY*PP*2)                      // 6300
#define SMEM_FLOATS (OFS_H + RY*HP*4)           // +10920 = 17220 (68880 B)

__device__ float g_partial[NBLK];
__device__ unsigned int g_flag;   // zero-init; last block resets it

__device__ __forceinline__ ull pack2(float lo, float hi) {
    ull r; asm("mov.b64 %0,{%1,%2};" : "=l"(r) : "f"(lo), "f"(hi)); return r;
}
__device__ __forceinline__ float2 unpack2(ull v) {
    float2 r; asm("mov.b64 {%0,%1},%2;" : "=f"(r.x), "=f"(r.y) : "l"(v)); return r;
}
__device__ __forceinline__ ull fma2(ull a, ull b, ull c) {
    ull d; asm("fma.rn.f32x2 %0,%1,%2,%3;" : "=l"(d) : "l"(a), "l"(b), "l"(c)); return d;
}
__device__ __forceinline__ ull mul2(ull a, ull b) {
    ull d; asm("mul.rn.f32x2 %0,%1,%2;" : "=l"(d) : "l"(a), "l"(b)); return d;
}

__global__ __launch_bounds__(NTHREADS, 3) void ssim_tile_kernel(
    const float* __restrict__ img1,
    const float* __restrict__ img2,
    const float* __restrict__ window,
    float* __restrict__ out)
{
    extern __shared__ float smem[];
    float* sxyF = smem + OFS_SXY;                // (u,v) pairs, one channel
    float* hF   = smem + OFS_H;                  // (U,V,Su,Sv) float4 per column

    const int tid  = threadIdx.x;
    const int wid  = tid >> 5;
    const int lane = tid & 31;

    // ---- separable taps: w2d = g g^T exactly, so g_k = w2d[5][k] / sqrt(w2d[5][5])
    ull wwr[KW];                                  // (w,w) broadcast pairs in regs
    {
        float g5 = sqrtf(window[5 * KW + 5]);
        #pragma unroll
        for (int k = 0; k < KW; k++) {
            float w = window[5 * KW + k] / g5;
            wwr[k] = pack2(w, w);
        }
    }

    const int row0 = (int)blockIdx.y * TY - HALO;
    const int col0 = (int)blockIdx.x * TX - HALO;

    float lsum = 0.f;

    for (int c = 0; c < NCH; c++) {
        // ---------- per-channel load: HWC global -> (u,v) pairs in smem -------
        for (int idx = tid; idx < RY * RX; idx += NTHREADS) {
            int r = idx / RX;
            int p = idx - r * RX;
            int gr = row0 + r, gc = col0 + p;
            float v1 = 0.f, v2 = 0.f;
            if (gr >= 0 && gr < IMH && gc >= 0 && gc < IMW) {
                int off = (gr * IMW + gc) * NCH + c;
                v1 = img1[off];
                v2 = img2[off];
            }
            // zero padding commutes with (u,v) = (x+y, x-y)
            ((float2*)sxyF)[r * PP + p] = make_float2(v1 + v2, v1 - v2);
        }
        __syncthreads();

        // ---------- horizontal pass: 8-wide register-blocked, fully packed ----
        for (int idx = tid; idx < RY * 8; idx += NTHREADS) {   // 336 items
            int r  = idx % RY;
            int j0 = (idx / RY) << 3;
            const ull* puv = (const ull*)sxyF + r * PP + j0;

            ull auv[8], ass[8];
            #pragma unroll
            for (int o = 0; o < 8; o++) { auv[o] = 0; ass[o] = 0; }

            #pragma unroll
            for (int t = 0; t < 18; t++) {        // 8 + KW - 1
                ull vuv = puv[t];
                ull vss = mul2(vuv, vuv);
                #pragma unroll
                for (int o = 0; o < 8; o++) {
                    int k = t - o;
                    if (k >= 0 && k < KW) {       // compile-time resolved
                        auv[o] = fma2(wwr[k], vuv, auv[o]);
                        ass[o] = fma2(wwr[k], vss, ass[o]);
                    }
                }
            }
            float4* dst = (float4*)hF + r * HP + j0;
            #pragma unroll
            for (int o = 0; o < 8; o++) {
                float2 a = unpack2(auv[o]);
                float2 b = unpack2(ass[o]);
                dst[o] = make_float4(a.x, a.y, b.x, b.y);
            }
        }
        __syncthreads();   // sxy reads done; h writes visible

        // ---------- vertical pass: 8-stack, 256 threads single exact wave -----
        {
            int tx  = tid & 63;                   // column 0..63
            int ty0 = (tid >> 6) << 3;            // stack base row 0/8/16/24
            ull aU[8], aS[8];
            #pragma unroll
            for (int o = 0; o < 8; o++) { aU[o] = 0; aS[o] = 0; }

            #pragma unroll
            for (int t = 0; t < 18; t++) {
                int r = ty0 + t;
                float4 h = ((const float4*)hF)[r * HP + tx];
                ull huv = pack2(h.x, h.y);
                ull hss = pack2(h.z, h.w);
                #pragma unroll
                for (int o = 0; o < 8; o++) {
                    int k = t - o;
                    if (k >= 0 && k < KW) {
                        aU[o] = fma2(wwr[k], huv, aU[o]);
                        aS[o] = fma2(wwr[k], hss, aS[o]);
                    }
                }
            }
            #pragma unroll
            for (int o = 0; o < 8; o++) {
                float2 uv = unpack2(aU[o]);      // U = mu1+mu2, V = mu1-mu2
                float2 ss = unpack2(aS[o]);      // Su = E[u^2], Sv = E[v^2]
                float U2 = uv.x * uv.x;
                float V2 = uv.y * uv.y;
                float A  = ss.x - U2;            // = s1+s2+2*s12 (x2 scale)
                float B  = ss.y - V2;            // = s1+s2-2*s12 (x2 scale)
                float num = fmaf(0.5f, U2 - V2, C1) * fmaf(0.5f, A - B, C2);
                float den = fmaf(0.5f, U2 + V2, C1) * fmaf(0.5f, A + B, C2);
                lsum += __fdividef(num, den);
            }
        }
        __syncthreads();   // h reads done before next channel load overwrites sxy/h
    }

    // ---------- block reduction ----------
    #pragma unroll
    for (int s = 16; s > 0; s >>= 1)
        lsum += __shfl_xor_sync(0xffffffffu, lsum, s);
    __shared__ float red[8];
    if (lane == 0) red[wid] = lsum;
    __syncthreads();
    if (tid == 0) {
        float bs = 0.f;
        #pragma unroll
        for (int i = 0; i < 8; i++) bs += red[i];
        g_partial[blockIdx.y * GX + blockIdx.x] = bs;
    }

    // ---------- last-block finalize (no second launch) ----------
    __shared__ bool amLast;
    __threadfence();
    if (tid == 0) {
        unsigned int n = atomicAdd(&g_flag, 1u);
        amLast = (n == (unsigned)(NBLK - 1));
    }
    __syncthreads();
    if (amLast) {
        double s = 0.0;
        for (int i = tid; i < NBLK; i += NTHREADS)
            s += (double)g_partial[i];
        #pragma unroll
        for (int sft = 16; sft > 0; sft >>= 1)
            s += __shfl_xor_sync(0xffffffffu, s, sft);
        __shared__ double rd[8];
        if (lane == 0) rd[wid] = s;
        __syncthreads();
        if (tid == 0) {
            double t = 0.0;
            #pragma unroll
            for (int i = 0; i < 8; i++) t += rd[i];
            out[0] = (float)(1.0 - t / ((double)IMH * IMW * NCH));
            g_flag = 0;                 // reset for next graph replay
        }
    }
}

extern "C" void kernel_launch(void* const* d_in, const int* in_sizes, int n_in,
                              void* d_out, int out_size)
{
    const float* img1 = (const float*)d_in[0];
    const float* img2 = (const float*)d_in[1];
    const float* win  = (const float*)d_in[2];
    float* out = (float*)d_out;
    (void)in_sizes; (void)n_in; (void)out_size;

    const size_t SMEM = (size_t)SMEM_FLOATS * sizeof(float);   // 68880 B
    cudaFuncSetAttribute(ssim_tile_kernel,
                         cudaFuncAttributeMaxDynamicSharedMemorySize, (int)SMEM);

    dim3 grid(GX, GY);
    ssim_tile_kernel<<<grid, NTHREADS, SMEM>>>(img1, img2, win, out);
}